// round 10
// baseline (speedup 1.0000x reference)
#include <cuda_runtime.h>
#include <cuda_fp16.h>
#include <cstdint>

#define TAU_F 0.5f

static const int MROWS = 6272;     // 32 * 196
static const int CDIM  = 768;
static const int NDIM  = 2304;     // 3 * 768
static const int TT    = 10;
static const int RRK   = 16;

// ---------------- device scratch (static allocation is allowed) --------------
__device__ float  g_sumsq[40];                   // [Aq(10) Bq(10) Av(10) Bv(10)]
__device__ __half g_Wch[2304u * 768u];           // W_qkv + LoRA deltas, f16-rn
__device__ __half g_xh [6272u * 768u];           // x, f16-rn

// ---------------- helpers ----------------------------------------------------
__device__ __forceinline__ uint32_t smem_to_u32(const void* smem_ptr) {
    uint32_t addr;
    asm("{ .reg .u64 tmp; cvta.to.shared.u64 tmp, %1; cvt.u32.u64 %0, tmp; }"
        : "=r"(addr) : "l"(smem_ptr));
    return addr;
}

#define CP_ASYNC16(dst, src) \
    asm volatile("cp.async.cg.shared.global [%0], [%1], 16;" :: "r"((uint32_t)(dst)), "l"(src) : "memory")

#define CP_COMMIT() asm volatile("cp.async.commit_group;" ::: "memory")
#define CP_WAIT(n)  asm volatile("cp.async.wait_group %0;" :: "n"(n) : "memory")

// ldmatrix x4 (baseline PTX sm_75+)
__device__ __forceinline__ void ldsm4(uint32_t* r, uint32_t addr) {
    asm volatile("ldmatrix.sync.aligned.m8n8.x4.shared.b16 {%0,%1,%2,%3}, [%4];"
        : "=r"(r[0]), "=r"(r[1]), "=r"(r[2]), "=r"(r[3]) : "r"(addr));
}

// m16n8k16 f16 mma, f32 accumulate (baseline PTX sm_80+): 4096 FLOP/instr
__device__ __forceinline__ void mma16(float* c, const uint32_t* A, const uint32_t* B) {
    asm volatile(
        "mma.sync.aligned.m16n8k16.row.col.f32.f16.f16.f32 "
        "{%0,%1,%2,%3}, {%4,%5,%6,%7}, {%8,%9}, {%0,%1,%2,%3};"
        : "+f"(c[0]), "+f"(c[1]), "+f"(c[2]), "+f"(c[3])
        : "r"(A[0]), "r"(A[1]), "r"(A[2]), "r"(A[3]), "r"(B[0]), "r"(B[1]));
}

// ---------------- prologue: fused x->f16 conversion + Frobenius norms --------
// blocks [0, 4704): cvt;  blocks [4704, 4744): norms (40 blocks)
__global__ void prol_kernel(const float* __restrict__ x,
                            const float* __restrict__ Aq, const float* __restrict__ Bq,
                            const float* __restrict__ Av, const float* __restrict__ Bv) {
    if (blockIdx.x < 4704) {
        int i = blockIdx.x * 256 + threadIdx.x;       // exactly MROWS*CDIM/4 elems
        float4 v = ((const float4*)x)[i];
        __half2 h0 = __floats2half2_rn(v.x, v.y);
        __half2 h1 = __floats2half2_rn(v.z, v.w);
        uint2 pk;
        pk.x = *reinterpret_cast<uint32_t*>(&h0);
        pk.y = *reinterpret_cast<uint32_t*>(&h1);
        ((uint2*)g_xh)[i] = pk;
        return;
    }
    int bid = blockIdx.x - 4704;
    const float* mats[4] = {Aq, Bq, Av, Bv};
    int mi = bid / 10;
    int t  = bid % 10;
    const float* p = mats[mi] + (size_t)t * (RRK * CDIM);
    float s = 0.f;
    for (int i = threadIdx.x; i < RRK * CDIM; i += 256) {
        float v = p[i];
        s += v * v;
    }
    __shared__ float red[256];
    red[threadIdx.x] = s;
    __syncthreads();
    for (int st = 128; st > 0; st >>= 1) {
        if (threadIdx.x < st) red[threadIdx.x] += red[threadIdx.x + st];
        __syncthreads();
    }
    if (threadIdx.x == 0) g_sumsq[bid] = red[0];
}

// grid (12, 36) x 256: g_Wch = f16_rn(W_qkv + LoRA deltas); scales computed inline
__global__ void build_wc_kernel(const float* __restrict__ W,
                                const float* __restrict__ Aq, const float* __restrict__ Bq,
                                const float* __restrict__ Av, const float* __restrict__ Bv,
                                const float* __restrict__ lq, const float* __restrict__ lv) {
    int i0 = blockIdx.x * 64;      // input-dim tile (0..767)
    int o0 = blockIdx.y * 64;      // output-dim tile (0..2303)
    int band = o0 / CDIM;          // 0 = q-rows, 1 = k-rows (copy), 2 = v-rows
    int tid = threadIdx.x;

    if (band == 1) {               // plain copy + f16 round
        for (int u = 0; u < 16; u++) {
            int e = tid + u * 256;
            int oo = e >> 6, ii = e & 63;
            size_t idx = (size_t)(o0 + oo) * CDIM + i0 + ii;
            g_Wch[idx] = __float2half_rn(W[idx]);
        }
        return;
    }

    const float* A  = band ? Av : Aq;
    const float* Bm = band ? Bv : Bq;
    int lo0 = (band == 2) ? (o0 - 2 * CDIM) : o0;   // local row within [0,768)

    // inline fused scales: softmax(logits/tau) / (||A||*||B||)  (10 exps, cheap)
    __shared__ float sc[TT];
    if (tid == 0) {
        const float* l = band ? lv : lq;
        const float* ss = g_sumsq + (band ? 20 : 0);
        float mx = -1e30f;
        for (int t = 0; t < TT; t++) mx = fmaxf(mx, l[t] / TAU_F);
        float e[TT], sum = 0.f;
        for (int t = 0; t < TT; t++) { e[t] = expf(l[t] / TAU_F - mx); sum += e[t]; }
        for (int t = 0; t < TT; t++)
            sc[t] = (e[t] / sum) * rsqrtf(ss[t] * ss[10 + t]);
    }

    __shared__ float sA[RRK][64];
    __shared__ float sB[64][RRK];

    int to = tid >> 4, ti = tid & 15;
    float acc[4][4] = {};

    for (int t = 0; t < TT; t++) {
        __syncthreads();
        #pragma unroll
        for (int u = 0; u < 4; u++) {
            int e = tid + u * 256;
            int r = e >> 6, ii = e & 63;
            sA[r][ii] = A[((size_t)t * RRK + r) * CDIM + i0 + ii];
        }
        float s = sc[t];
        #pragma unroll
        for (int u = 0; u < 4; u++) {
            int e = tid + u * 256;
            int oo = e >> 4, r = e & 15;
            sB[oo][r] = Bm[((size_t)t * CDIM + lo0 + oo) * RRK + r] * s;
        }
        __syncthreads();
        #pragma unroll
        for (int r = 0; r < RRK; r++) {
            float a[4], b[4];
            #pragma unroll
            for (int x = 0; x < 4; x++) { a[x] = sA[r][ti * 4 + x]; b[x] = sB[to * 4 + x][r]; }
            #pragma unroll
            for (int x = 0; x < 4; x++)
                #pragma unroll
                for (int y = 0; y < 4; y++)
                    acc[x][y] += b[x] * a[y];
        }
    }

    #pragma unroll
    for (int x = 0; x < 4; x++) {
        size_t row = (size_t)(o0 + to * 4 + x);
        #pragma unroll
        for (int y = 0; y < 4; y++) {
            size_t idx = row * CDIM + i0 + ti * 4 + y;
            g_Wch[idx] = __float2half_rn(W[idx] + acc[x][y]);
        }
    }
}

// ---------------- main GEMM: out = g_xh @ g_Wch^T + bias ---------------------
// CTA tile 128(M) x 96(N), BK=64 f16, 3-stage cp.async ring, 2 CTAs/SM.
// 384 threads = 12 warps in 4(M) x 3(N); warp tile 32x32 = 2x4 m16n8 tiles.
// 24 warps/SM = 6 warps/SMSP to hide barrier + LDSM->MMA bubbles.

static const int BN = 96;
static const int KT = CDIM / 64;          // 12 k-tiles
static const int A_BYTES = 128 * 128;     // 16384 (128 rows x 64 halves)
static const int STAGE_BYTES = A_BYTES + BN * 128;   // 28672
static const int SMEM_DYN = 3 * STAGE_BYTES;         // 86016 -> 2 CTAs/SM

__global__ void __launch_bounds__(384, 2)
gemm_kernel(const float* __restrict__ bias, float* __restrict__ out) {
    extern __shared__ char smem[];
    const uint32_t sbase = smem_to_u32(smem);

    const int tid = threadIdx.x;
    const int wid = tid >> 5, lid = tid & 31;
    const int lr  = lid >> 2, lc = lid & 3;          // mma fragment coords
    const int sub = lid >> 3, r8 = lid & 7;          // ldmatrix coords
    const int n0  = blockIdx.x * BN;
    const int m0  = blockIdx.y * 128;
    const int mw  = (wid & 3) * 32;                  // 4 M positions
    const int nw  = (wid >> 2) * 32;                 // 3 N positions

    const __half* gA = g_xh  + (size_t)m0 * CDIM;
    const __half* gB = g_Wch + (size_t)n0 * CDIM;

    // loader: granule g -> row = g>>3, c8 = g&7; A 1024 granules, B 768 granules
    auto goff = [](int g) {
        int row = g >> 3, c8 = g & 7;
        return (uint32_t)row * 128 + (uint32_t)(c8 ^ (row & 7)) * 16;
    };
    const uint32_t aoff0 = goff(tid), aoff1 = goff(tid + 384), aoff2 = goff(tid + 768);
    const uint32_t boff0 = aoff0, boff1 = aoff1;     // same mapping, rows 0..95
    const bool a2_ok = (tid < 256);                  // granules 768..1023

    auto load_stage = [&](int s) {
        uint32_t st = sbase + (uint32_t)(s % 3) * STAGE_BYTES;
        int k0 = s * 64;              // in halves
        const __half* gAk = gA + k0;
        const __half* gBk = gB + k0;
        // A rows: tid>>3, (tid+384)>>3, (tid+768)>>3
        CP_ASYNC16(st + aoff0, gAk + (size_t)(tid >> 3) * CDIM + (tid & 7) * 8);
        CP_ASYNC16(st + aoff1, gAk + (size_t)((tid + 384) >> 3) * CDIM + (tid & 7) * 8);
        if (a2_ok)
            CP_ASYNC16(st + aoff2, gAk + (size_t)((tid + 768) >> 3) * CDIM + (tid & 7) * 8);
        // B rows 0..95
        CP_ASYNC16(st + A_BYTES + boff0, gBk + (size_t)(tid >> 3) * CDIM + (tid & 7) * 8);
        CP_ASYNC16(st + A_BYTES + boff1, gBk + (size_t)((tid + 384) >> 3) * CDIM + (tid & 7) * 8);
    };

    // ldmatrix per-thread row terms (byte offsets within a stage)
    const int kgA = sub >> 1;
    uint32_t rowTermA[2];
    #pragma unroll
    for (int mt = 0; mt < 2; mt++)
        rowTermA[mt] = (uint32_t)(mw + mt * 16 + (sub & 1) * 8 + r8) * 128;
    const int kgB = sub & 1;
    uint32_t rowTermB[2];
    #pragma unroll
    for (int p = 0; p < 2; p++)
        rowTermB[p] = (uint32_t)A_BYTES + (uint32_t)(nw + p * 16 + (sub >> 1) * 8 + r8) * 128;

    float acc[2][4][4] = {};

    load_stage(0); CP_COMMIT();
    load_stage(1); CP_COMMIT();

    for (int i = 0; i < KT; ++i) {
        CP_WAIT(1);                                  // stage i resident
        __syncthreads();                             // all warps done with slot (i+2)%3
        if (i + 2 < KT) load_stage(i + 2);
        CP_COMMIT();                                 // keep group bookkeeping uniform

        uint32_t st = sbase + (uint32_t)(i % 3) * STAGE_BYTES;

        #pragma unroll
        for (int ks = 0; ks < 4; ks++) {             // 4 x k16 chunks per BK=64
            uint32_t gA_ = (uint32_t)(((2 * ks + kgA) ^ r8) * 16);
            uint32_t gB_ = (uint32_t)(((2 * ks + kgB) ^ r8) * 16);

            uint32_t a[2][4];
            #pragma unroll
            for (int mt = 0; mt < 2; mt++)
                ldsm4(a[mt], st + rowTermA[mt] + gA_);
            uint32_t b[2][4];   // b[p] = {b0(nt=2p), b1(nt=2p), b0(nt=2p+1), b1(nt=2p+1)}
            #pragma unroll
            for (int p = 0; p < 2; p++)
                ldsm4(b[p], st + rowTermB[p] + gB_);

            #pragma unroll
            for (int mt = 0; mt < 2; mt++)
                #pragma unroll
                for (int nt = 0; nt < 4; nt++)
                    mma16(acc[mt][nt], a[mt], &b[nt >> 1][(nt & 1) * 2]);
        }
    }

    // epilogue: regs -> gmem with bias, float2 stores
    float2 bb[4];
    #pragma unroll
    for (int nt = 0; nt < 4; nt++)
        bb[nt] = *(const float2*)(bias + n0 + nw + nt * 8 + lc * 2);

    #pragma unroll
    for (int mt = 0; mt < 2; mt++) {
        #pragma unroll
        for (int nt = 0; nt < 4; nt++) {
            int m = m0 + mw + mt * 16 + lr;
            int n = n0 + nw + nt * 8 + lc * 2;
            float2 v0 = make_float2(acc[mt][nt][0] + bb[nt].x, acc[mt][nt][1] + bb[nt].y);
            float2 v1 = make_float2(acc[mt][nt][2] + bb[nt].x, acc[mt][nt][3] + bb[nt].y);
            *(float2*)(out + (size_t)m * NDIM + n)       = v0;
            *(float2*)(out + (size_t)(m + 8) * NDIM + n) = v1;
        }
    }
}

// ---------------- launch ------------------------------------------------------
extern "C" void kernel_launch(void* const* d_in, const int* in_sizes, int n_in,
                              void* d_out, int out_size) {
    const float* x  = (const float*)d_in[0];
    const float* W  = (const float*)d_in[1];
    const float* b  = (const float*)d_in[2];
    const float* Aq = (const float*)d_in[3];
    const float* Bq = (const float*)d_in[4];
    const float* Av = (const float*)d_in[5];
    const float* Bv = (const float*)d_in[6];
    const float* lq = (const float*)d_in[7];
    const float* lv = (const float*)d_in[8];
    float* out = (float*)d_out;

    prol_kernel<<<4744, 256>>>(x, Aq, Bq, Av, Bv);
    build_wc_kernel<<<dim3(12, 36), 256>>>(W, Aq, Bq, Av, Bv, lq, lv);

    cudaFuncSetAttribute(gemm_kernel, cudaFuncAttributeMaxDynamicSharedMemorySize, SMEM_DYN);
    gemm_kernel<<<dim3(NDIM / BN, MROWS / 128), 384, SMEM_DYN>>>(b, out);
}

// round 12
// speedup vs baseline: 1.4485x; 1.4485x over previous
#include <cuda_runtime.h>
#include <cuda_fp16.h>
#include <cstdint>

#define TAU_F 0.5f

static const int MROWS = 6272;     // 32 * 196
static const int CDIM  = 768;
static const int NDIM  = 2304;     // 3 * 768
static const int TT    = 10;
static const int RRK   = 16;

// ---------------- device scratch (static allocation is allowed) --------------
__device__ float  g_sumsq[40];                   // [Aq(10) Bq(10) Av(10) Bv(10)]
__device__ int    g_sem;                         // norms-done semaphore (memset per launch)
__device__ __half g_Wch[2304u * 768u];           // W_qkv + LoRA deltas, f16-rn
__device__ __half g_xh [6272u * 768u];           // x, f16-rn

// ---------------- helpers ----------------------------------------------------
__device__ __forceinline__ uint32_t smem_to_u32(const void* smem_ptr) {
    uint32_t addr;
    asm("{ .reg .u64 tmp; cvta.to.shared.u64 tmp, %1; cvt.u32.u64 %0, tmp; }"
        : "=r"(addr) : "l"(smem_ptr));
    return addr;
}

#define CP_ASYNC16(dst, src) \
    asm volatile("cp.async.cg.shared.global [%0], [%1], 16;" :: "r"((uint32_t)(dst)), "l"(src) : "memory")

#define CP_COMMIT() asm volatile("cp.async.commit_group;" ::: "memory")
#define CP_WAIT(n)  asm volatile("cp.async.wait_group %0;" :: "n"(n) : "memory")

// ldmatrix x4 (baseline PTX sm_75+)
__device__ __forceinline__ void ldsm4(uint32_t* r, uint32_t addr) {
    asm volatile("ldmatrix.sync.aligned.m8n8.x4.shared.b16 {%0,%1,%2,%3}, [%4];"
        : "=r"(r[0]), "=r"(r[1]), "=r"(r[2]), "=r"(r[3]) : "r"(addr));
}

// m16n8k16 f16 mma, f32 accumulate (baseline PTX sm_80+): 4096 FLOP/instr
__device__ __forceinline__ void mma16(float* c, const uint32_t* A, const uint32_t* B) {
    asm volatile(
        "mma.sync.aligned.m16n8k16.row.col.f32.f16.f16.f32 "
        "{%0,%1,%2,%3}, {%4,%5,%6,%7}, {%8,%9}, {%0,%1,%2,%3};"
        : "+f"(c[0]), "+f"(c[1]), "+f"(c[2]), "+f"(c[3])
        : "r"(A[0]), "r"(A[1]), "r"(A[2]), "r"(A[3]), "r"(B[0]), "r"(B[1]));
}

// ---------------- single fused prologue kernel -------------------------------
// block roles (scheduled roughly in bid order):
//   [0, 40)            : Frobenius sumsq of Aq/Bq/Av/Bv, then g_sem++
//   [40, 40+4704)      : x -> f16 conversion (independent, fills the machine)
//   [4744, 4744+432)   : build Wc = f16(W + LoRA delta); bands 0/2 spin on g_sem
static const int NB_NORM = 40;
static const int NB_CVT  = 4704;
static const int NB_WC   = 432;          // 12 x 36

__global__ void __launch_bounds__(256)
prologue_kernel(const float* __restrict__ x, const float* __restrict__ W,
                const float* __restrict__ Aq, const float* __restrict__ Bq,
                const float* __restrict__ Av, const float* __restrict__ Bv,
                const float* __restrict__ lq, const float* __restrict__ lv) {
    const int bid = blockIdx.x;
    const int tid = threadIdx.x;

    // ---- role 1: norms --------------------------------------------------
    if (bid < NB_NORM) {
        const float* mats[4] = {Aq, Bq, Av, Bv};
        int mi = bid / 10, t = bid % 10;
        const float* p = mats[mi] + (size_t)t * (RRK * CDIM);
        float s = 0.f;
        for (int i = tid; i < RRK * CDIM; i += 256) {
            float v = p[i];
            s += v * v;
        }
        __shared__ float red[256];
        red[tid] = s;
        __syncthreads();
        for (int st = 128; st > 0; st >>= 1) {
            if (tid < st) red[tid] += red[tid + st];
            __syncthreads();
        }
        if (tid == 0) {
            g_sumsq[bid] = red[0];
            __threadfence();
            atomicAdd(&g_sem, 1);
        }
        return;
    }

    // ---- role 2: x -> f16 ----------------------------------------------
    if (bid < NB_NORM + NB_CVT) {
        int i = (bid - NB_NORM) * 256 + tid;          // exactly MROWS*CDIM/4 elems
        float4 v = ((const float4*)x)[i];
        __half2 h0 = __floats2half2_rn(v.x, v.y);
        __half2 h1 = __floats2half2_rn(v.z, v.w);
        uint2 pk;
        pk.x = *reinterpret_cast<uint32_t*>(&h0);
        pk.y = *reinterpret_cast<uint32_t*>(&h1);
        ((uint2*)g_xh)[i] = pk;
        return;
    }

    // ---- role 3: build Wc -----------------------------------------------
    const int wc = bid - (NB_NORM + NB_CVT);
    int i0 = (wc % 12) * 64;       // input-dim tile (0..767)
    int o0 = (wc / 12) * 64;       // output-dim tile (0..2303)
    int band = o0 / CDIM;          // 0 = q-rows, 1 = k-rows (copy), 2 = v-rows

    if (band == 1) {               // plain copy + f16 round, no dependency
        for (int u = 0; u < 16; u++) {
            int e = tid + u * 256;
            int oo = e >> 6, ii = e & 63;
            size_t idx = (size_t)(o0 + oo) * CDIM + i0 + ii;
            g_Wch[idx] = __float2half_rn(W[idx]);
        }
        return;
    }

    const float* A  = band ? Av : Aq;
    const float* Bm = band ? Bv : Bq;
    int lo0 = (band == 2) ? (o0 - 2 * CDIM) : o0;   // local row within [0,768)

    // wait for norms, then fused scales: softmax(logits/tau)/(||A||*||B||)
    __shared__ float sc[TT];
    if (tid == 0) {
        while (*((volatile int*)&g_sem) < NB_NORM) { }
        __threadfence();
        const float* l = band ? lv : lq;
        const float* ss = g_sumsq + (band ? 20 : 0);
        float mx = -1e30f;
        for (int t = 0; t < TT; t++) mx = fmaxf(mx, l[t] / TAU_F);
        float e[TT], sum = 0.f;
        for (int t = 0; t < TT; t++) { e[t] = expf(l[t] / TAU_F - mx); sum += e[t]; }
        for (int t = 0; t < TT; t++)
            sc[t] = (e[t] / sum) * rsqrtf(ss[t] * ss[10 + t]);
    }

    __shared__ float sA[RRK][64];
    __shared__ float sB[64][RRK];

    int to = tid >> 4, ti = tid & 15;
    float acc[4][4] = {};

    for (int t = 0; t < TT; t++) {
        __syncthreads();
        #pragma unroll
        for (int u = 0; u < 4; u++) {
            int e = tid + u * 256;
            int r = e >> 6, ii = e & 63;
            sA[r][ii] = A[((size_t)t * RRK + r) * CDIM + i0 + ii];
        }
        float s = sc[t];
        #pragma unroll
        for (int u = 0; u < 4; u++) {
            int e = tid + u * 256;
            int oo = e >> 4, r = e & 15;
            sB[oo][r] = Bm[((size_t)t * CDIM + lo0 + oo) * RRK + r] * s;
        }
        __syncthreads();
        #pragma unroll
        for (int r = 0; r < RRK; r++) {
            float a[4], b[4];
            #pragma unroll
            for (int xq = 0; xq < 4; xq++) { a[xq] = sA[r][ti * 4 + xq]; b[xq] = sB[to * 4 + xq][r]; }
            #pragma unroll
            for (int xq = 0; xq < 4; xq++)
                #pragma unroll
                for (int y = 0; y < 4; y++)
                    acc[xq][y] += b[xq] * a[y];
        }
    }

    #pragma unroll
    for (int xq = 0; xq < 4; xq++) {
        size_t row = (size_t)(o0 + to * 4 + xq);
        #pragma unroll
        for (int y = 0; y < 4; y++) {
            size_t idx = row * CDIM + i0 + ti * 4 + y;
            g_Wch[idx] = __float2half_rn(W[idx] + acc[xq][y]);
        }
    }
}

// ---------------- main GEMM: out = g_xh @ g_Wch^T + bias ---------------------
// (R9 config, measured 62.2us: 128x128 CTA, BK=64, 3-stage ring, 2 CTAs/SM,
//  8 warps in 2(M) x 4(N), warp tile 64x32 = 4x4 m16n8 tiles, ldmatrix.x4)

static const int KT = CDIM / 64;          // 12 k-tiles
static const int STAGE_BYTES = 32768;     // A 16KB + B 16KB
static const int SMEM_DYN = 3 * STAGE_BYTES;   // 96KB -> 2 CTAs/SM

__global__ void __launch_bounds__(256, 2)
gemm_kernel(const float* __restrict__ bias, float* __restrict__ out) {
    extern __shared__ char smem[];
    const uint32_t sbase = smem_to_u32(smem);

    const int tid = threadIdx.x;
    const int wid = tid >> 5, lid = tid & 31;
    const int lr  = lid >> 2, lc = lid & 3;          // mma fragment coords
    const int sub = lid >> 3, r8 = lid & 7;          // ldmatrix coords
    const int n0  = blockIdx.x * 128;
    const int m0  = blockIdx.y * 128;
    const int mw  = (wid & 1) * 64;                  // 2 M-halves
    const int nw  = (wid >> 1) * 32;                 // 4 N-quarters

    const __half* gA = g_xh  + (size_t)m0 * CDIM;
    const __half* gB = g_Wch + (size_t)n0 * CDIM;

    const int lrow = tid >> 3;        // 0..31
    const int lc8  = tid & 7;         // 16B granule within 128B row

    auto load_stage = [&](int s) {
        uint32_t st = sbase + (uint32_t)(s % 3) * STAGE_BYTES;
        int k0 = s * 64;              // in halves
        #pragma unroll
        for (int q = 0; q < 4; q++) {             // A: 128 rows
            int row = lrow + q * 32;
            uint32_t off = (uint32_t)row * 128 + (uint32_t)(lc8 ^ (row & 7)) * 16;
            CP_ASYNC16(st + off, gA + (size_t)row * CDIM + k0 + lc8 * 8);
        }
        #pragma unroll
        for (int q = 0; q < 4; q++) {             // B: 128 rows
            int row = lrow + q * 32;
            uint32_t off = (uint32_t)row * 128 + (uint32_t)(lc8 ^ (row & 7)) * 16;
            CP_ASYNC16(st + 16384 + off, gB + (size_t)row * CDIM + k0 + lc8 * 8);
        }
    };

    // ldmatrix per-thread row terms (byte offsets within a stage)
    const int kgA = sub >> 1;
    uint32_t rowTermA[4];
    #pragma unroll
    for (int mt = 0; mt < 4; mt++)
        rowTermA[mt] = (uint32_t)(mw + mt * 16 + (sub & 1) * 8 + r8) * 128;
    const int kgB = sub & 1;
    uint32_t rowTermB[2];
    #pragma unroll
    for (int p = 0; p < 2; p++)
        rowTermB[p] = 16384u + (uint32_t)(nw + p * 16 + (sub >> 1) * 8 + r8) * 128;

    float acc[4][4][4] = {};

    load_stage(0); CP_COMMIT();
    load_stage(1); CP_COMMIT();

    for (int i = 0; i < KT; ++i) {
        CP_WAIT(1);                                  // stage i resident
        __syncthreads();                             // all warps done with slot (i+2)%3
        if (i + 2 < KT) load_stage(i + 2);
        CP_COMMIT();                                 // keep group bookkeeping uniform

        uint32_t st = sbase + (uint32_t)(i % 3) * STAGE_BYTES;

        #pragma unroll
        for (int ks = 0; ks < 4; ks++) {             // 4 x k16 chunks per BK=64
            uint32_t gA_ = (uint32_t)(((2 * ks + kgA) ^ r8) * 16);
            uint32_t gB_ = (uint32_t)(((2 * ks + kgB) ^ r8) * 16);

            uint32_t a[4][4];
            #pragma unroll
            for (int mt = 0; mt < 4; mt++)
                ldsm4(a[mt], st + rowTermA[mt] + gA_);
            uint32_t b[2][4];   // b[p] = {b0(nt=2p), b1(nt=2p), b0(nt=2p+1), b1(nt=2p+1)}
            #pragma unroll
            for (int p = 0; p < 2; p++)
                ldsm4(b[p], st + rowTermB[p] + gB_);

            #pragma unroll
            for (int mt = 0; mt < 4; mt++)
                #pragma unroll
                for (int nt = 0; nt < 4; nt++)
                    mma16(acc[mt][nt], a[mt], &b[nt >> 1][(nt & 1) * 2]);
        }
    }

    // epilogue: regs -> gmem with bias, float2 stores
    float2 bb[4];
    #pragma unroll
    for (int nt = 0; nt < 4; nt++)
        bb[nt] = *(const float2*)(bias + n0 + nw + nt * 8 + lc * 2);

    #pragma unroll
    for (int mt = 0; mt < 4; mt++) {
        #pragma unroll
        for (int nt = 0; nt < 4; nt++) {
            int m = m0 + mw + mt * 16 + lr;
            int n = n0 + nw + nt * 8 + lc * 2;
            float2 v0 = make_float2(acc[mt][nt][0] + bb[nt].x, acc[mt][nt][1] + bb[nt].y);
            float2 v1 = make_float2(acc[mt][nt][2] + bb[nt].x, acc[mt][nt][3] + bb[nt].y);
            *(float2*)(out + (size_t)m * NDIM + n)       = v0;
            *(float2*)(out + (size_t)(m + 8) * NDIM + n) = v1;
        }
    }
}

// ---------------- launch ------------------------------------------------------
extern "C" void kernel_launch(void* const* d_in, const int* in_sizes, int n_in,
                              void* d_out, int out_size) {
    const float* x  = (const float*)d_in[0];
    const float* W  = (const float*)d_in[1];
    const float* b  = (const float*)d_in[2];
    const float* Aq = (const float*)d_in[3];
    const float* Bq = (const float*)d_in[4];
    const float* Av = (const float*)d_in[5];
    const float* Bv = (const float*)d_in[6];
    const float* lq = (const float*)d_in[7];
    const float* lv = (const float*)d_in[8];
    float* out = (float*)d_out;

    // reset the norms semaphore every replay (async memset is capturable)
    void* sem_addr = nullptr;
    cudaGetSymbolAddress(&sem_addr, g_sem);
    cudaMemsetAsync(sem_addr, 0, sizeof(int));

    prologue_kernel<<<NB_NORM + NB_CVT + NB_WC, 256>>>(x, W, Aq, Bq, Av, Bv, lq, lv);

    cudaFuncSetAttribute(gemm_kernel, cudaFuncAttributeMaxDynamicSharedMemorySize, SMEM_DYN);
    gemm_kernel<<<dim3(NDIM / 128, MROWS / 128), 256, SMEM_DYN>>>(b, out);
}

// round 14
// speedup vs baseline: 1.6076x; 1.1098x over previous
#include <cuda_runtime.h>
#include <cuda_fp16.h>
#include <cstdint>

#define TAU_F 0.5f

static const int MROWS = 6272;     // 32 * 196
static const int CDIM  = 768;
static const int NDIM  = 2304;     // 3 * 768
static const int TT    = 10;
static const int RRK   = 16;

// ---------------- device scratch (static allocation is allowed) --------------
__device__ float  g_sumsq[40];                   // [Aq(10) Bq(10) Av(10) Bv(10)]
__device__ float  g_scale[2][10];                // [q, v] per-task fused scales
__device__ __half g_Wch[2304u * 768u];           // W_qkv + LoRA deltas, f16-rn
__device__ __half g_xh [6272u * 768u];           // x, f16-rn

// ---------------- helpers ----------------------------------------------------
__device__ __forceinline__ uint32_t smem_to_u32(const void* smem_ptr) {
    uint32_t addr;
    asm("{ .reg .u64 tmp; cvta.to.shared.u64 tmp, %1; cvt.u32.u64 %0, tmp; }"
        : "=r"(addr) : "l"(smem_ptr));
    return addr;
}

#define CP_ASYNC16(dst, src) \
    asm volatile("cp.async.cg.shared.global [%0], [%1], 16;" :: "r"((uint32_t)(dst)), "l"(src) : "memory")

#define CP_COMMIT() asm volatile("cp.async.commit_group;" ::: "memory")
#define CP_WAIT(n)  asm volatile("cp.async.wait_group %0;" :: "n"(n) : "memory")

// ldmatrix x4 (baseline PTX sm_75+)
__device__ __forceinline__ void ldsm4(uint32_t* r, uint32_t addr) {
    asm volatile("ldmatrix.sync.aligned.m8n8.x4.shared.b16 {%0,%1,%2,%3}, [%4];"
        : "=r"(r[0]), "=r"(r[1]), "=r"(r[2]), "=r"(r[3]) : "r"(addr));
}

// m16n8k16 f16 mma, f32 accumulate (baseline PTX sm_80+): 4096 FLOP/instr
__device__ __forceinline__ void mma16(float* c, const uint32_t* A, const uint32_t* B) {
    asm volatile(
        "mma.sync.aligned.m16n8k16.row.col.f32.f16.f16.f32 "
        "{%0,%1,%2,%3}, {%4,%5,%6,%7}, {%8,%9}, {%0,%1,%2,%3};"
        : "+f"(c[0]), "+f"(c[1]), "+f"(c[2]), "+f"(c[3])
        : "r"(A[0]), "r"(A[1]), "r"(A[2]), "r"(A[3]), "r"(B[0]), "r"(B[1]));
}

// ---------------- prologue kernels (R8 split config — best measured) ---------

// grid 40 x 256: squared Frobenius norms of each [16,768] / [768,16] matrix
__global__ void norms_kernel(const float* __restrict__ Aq, const float* __restrict__ Bq,
                             const float* __restrict__ Av, const float* __restrict__ Bv) {
    const float* mats[4] = {Aq, Bq, Av, Bv};
    int mi = blockIdx.x / 10;
    int t  = blockIdx.x % 10;
    const float* p = mats[mi] + (size_t)t * (RRK * CDIM);
    float s = 0.f;
    for (int i = threadIdx.x; i < RRK * CDIM; i += 256) {
        float v = p[i];
        s += v * v;
    }
    __shared__ float red[256];
    red[threadIdx.x] = s;
    __syncthreads();
    for (int st = 128; st > 0; st >>= 1) {
        if (threadIdx.x < st) red[threadIdx.x] += red[threadIdx.x + st];
        __syncthreads();
    }
    if (threadIdx.x == 0) g_sumsq[blockIdx.x] = red[0];
}

// 1 x 32: softmax gates fused with 1/(||A||*||B||)
__global__ void scales_kernel(const float* __restrict__ lq, const float* __restrict__ lv) {
    if (threadIdx.x != 0) return;
    for (int b = 0; b < 2; b++) {
        const float* l = b ? lv : lq;
        float mx = -1e30f;
        for (int t = 0; t < TT; t++) mx = fmaxf(mx, l[t] / TAU_F);
        float e[TT], sum = 0.f;
        for (int t = 0; t < TT; t++) { e[t] = expf(l[t] / TAU_F - mx); sum += e[t]; }
        for (int t = 0; t < TT; t++) {
            float sa = g_sumsq[b * 20 + t];
            float sb = g_sumsq[b * 20 + 10 + t];
            g_scale[b][t] = (e[t] / sum) * rsqrtf(sa * sb);
        }
    }
}

// grid (12, 36) x 256: g_Wch = f16_rn(W_qkv + LoRA deltas)
__global__ void build_wc_kernel(const float* __restrict__ W,
                                const float* __restrict__ Aq, const float* __restrict__ Bq,
                                const float* __restrict__ Av, const float* __restrict__ Bv) {
    int i0 = blockIdx.x * 64;      // input-dim tile (0..767)
    int o0 = blockIdx.y * 64;      // output-dim tile (0..2303)
    int band = o0 / CDIM;          // 0 = q-rows, 1 = k-rows (copy), 2 = v-rows
    int tid = threadIdx.x;

    if (band == 1) {               // plain copy + f16 round
        for (int u = 0; u < 16; u++) {
            int e = tid + u * 256;
            int oo = e >> 6, ii = e & 63;
            size_t idx = (size_t)(o0 + oo) * CDIM + i0 + ii;
            g_Wch[idx] = __float2half_rn(W[idx]);
        }
        return;
    }

    const float* A  = band ? Av : Aq;
    const float* Bm = band ? Bv : Bq;
    const float* sc = g_scale[band ? 1 : 0];
    int lo0 = (band == 2) ? (o0 - 2 * CDIM) : o0;   // local row within [0,768)

    __shared__ float sA[RRK][64];
    __shared__ float sB[64][RRK];

    int to = tid >> 4, ti = tid & 15;
    float acc[4][4] = {};

    for (int t = 0; t < TT; t++) {
        __syncthreads();
        #pragma unroll
        for (int u = 0; u < 4; u++) {
            int e = tid + u * 256;
            int r = e >> 6, ii = e & 63;
            sA[r][ii] = A[((size_t)t * RRK + r) * CDIM + i0 + ii];
        }
        float s = sc[t];
        #pragma unroll
        for (int u = 0; u < 4; u++) {
            int e = tid + u * 256;
            int oo = e >> 4, r = e & 15;
            sB[oo][r] = Bm[((size_t)t * CDIM + lo0 + oo) * RRK + r] * s;
        }
        __syncthreads();
        #pragma unroll
        for (int r = 0; r < RRK; r++) {
            float a[4], b[4];
            #pragma unroll
            for (int xq = 0; xq < 4; xq++) { a[xq] = sA[r][ti * 4 + xq]; b[xq] = sB[to * 4 + xq][r]; }
            #pragma unroll
            for (int xq = 0; xq < 4; xq++)
                #pragma unroll
                for (int y = 0; y < 4; y++)
                    acc[xq][y] += b[xq] * a[y];
        }
    }

    #pragma unroll
    for (int xq = 0; xq < 4; xq++) {
        size_t row = (size_t)(o0 + to * 4 + xq);
        #pragma unroll
        for (int y = 0; y < 4; y++) {
            size_t idx = row * CDIM + i0 + ti * 4 + y;
            g_Wch[idx] = __float2half_rn(W[idx] + acc[xq][y]);
        }
    }
}

// grid 4704 x 256: g_xh = f16_rn(x)
__global__ void cvt_x_kernel(const float* __restrict__ x) {
    const int n4 = MROWS * CDIM / 4;
    for (int i = blockIdx.x * blockDim.x + threadIdx.x; i < n4; i += gridDim.x * blockDim.x) {
        float4 v = ((const float4*)x)[i];
        __half2 h0 = __floats2half2_rn(v.x, v.y);
        __half2 h1 = __floats2half2_rn(v.z, v.w);
        uint2 pk;
        pk.x = *reinterpret_cast<uint32_t*>(&h0);
        pk.y = *reinterpret_cast<uint32_t*>(&h1);
        ((uint2*)g_xh)[i] = pk;
    }
}

// ---------------- main GEMM: out = g_xh @ g_Wch^T + bias ---------------------
// R9 config (128x128 CTA, BK=64, 3-stage ring, 2 CTAs/SM, 8 warps 2Mx4N,
// warp tile 64x32) + double-buffered ldmatrix fragment prefetch:
// ks+1 fragments are fetched BEFORE the 16 MMAs of ks, hiding LDSM latency.

static const int KT = CDIM / 64;          // 12 k-tiles
static const int STAGE_BYTES = 32768;     // A 16KB + B 16KB
static const int SMEM_DYN = 3 * STAGE_BYTES;   // 96KB -> 2 CTAs/SM

__global__ void __launch_bounds__(256, 2)
gemm_kernel(const float* __restrict__ bias, float* __restrict__ out) {
    extern __shared__ char smem[];
    const uint32_t sbase = smem_to_u32(smem);

    const int tid = threadIdx.x;
    const int wid = tid >> 5, lid = tid & 31;
    const int lr  = lid >> 2, lc = lid & 3;          // mma fragment coords
    const int sub = lid >> 3, r8 = lid & 7;          // ldmatrix coords
    const int n0  = blockIdx.x * 128;
    const int m0  = blockIdx.y * 128;
    const int mw  = (wid & 1) * 64;                  // 2 M-halves
    const int nw  = (wid >> 1) * 32;                 // 4 N-quarters

    const __half* gA = g_xh  + (size_t)m0 * CDIM;
    const __half* gB = g_Wch + (size_t)n0 * CDIM;

    const int lrow = tid >> 3;        // 0..31
    const int lc8  = tid & 7;         // 16B granule within 128B row

    auto load_stage = [&](int s) {
        uint32_t st = sbase + (uint32_t)(s % 3) * STAGE_BYTES;
        int k0 = s * 64;              // in halves
        #pragma unroll
        for (int q = 0; q < 4; q++) {             // A: 128 rows
            int row = lrow + q * 32;
            uint32_t off = (uint32_t)row * 128 + (uint32_t)(lc8 ^ (row & 7)) * 16;
            CP_ASYNC16(st + off, gA + (size_t)row * CDIM + k0 + lc8 * 8);
        }
        #pragma unroll
        for (int q = 0; q < 4; q++) {             // B: 128 rows
            int row = lrow + q * 32;
            uint32_t off = (uint32_t)row * 128 + (uint32_t)(lc8 ^ (row & 7)) * 16;
            CP_ASYNC16(st + 16384 + off, gB + (size_t)row * CDIM + k0 + lc8 * 8);
        }
    };

    // ldmatrix per-thread row terms (byte offsets within a stage)
    const int kgA = sub >> 1;
    uint32_t rowTermA[4];
    #pragma unroll
    for (int mt = 0; mt < 4; mt++)
        rowTermA[mt] = (uint32_t)(mw + mt * 16 + (sub & 1) * 8 + r8) * 128;
    const int kgB = sub & 1;
    uint32_t rowTermB[2];
    #pragma unroll
    for (int p = 0; p < 2; p++)
        rowTermB[p] = 16384u + (uint32_t)(nw + p * 16 + (sub >> 1) * 8 + r8) * 128;

    float acc[4][4][4] = {};
    uint32_t aF[2][4][4];             // double-buffered A fragments
    uint32_t bF[2][2][4];             // double-buffered B fragments

    load_stage(0); CP_COMMIT();
    load_stage(1); CP_COMMIT();

    for (int i = 0; i < KT; ++i) {
        CP_WAIT(1);                                  // stage i resident
        __syncthreads();                             // all warps done with slot (i+2)%3
        if (i + 2 < KT) load_stage(i + 2);
        CP_COMMIT();                                 // keep group bookkeeping uniform

        uint32_t st = sbase + (uint32_t)(i % 3) * STAGE_BYTES;

        // prefetch ks=0 fragments
        {
            uint32_t gA_ = (uint32_t)((kgA ^ r8) * 16);
            uint32_t gB_ = (uint32_t)((kgB ^ r8) * 16);
            #pragma unroll
            for (int mt = 0; mt < 4; mt++) ldsm4(aF[0][mt], st + rowTermA[mt] + gA_);
            #pragma unroll
            for (int p = 0; p < 2; p++)    ldsm4(bF[0][p],  st + rowTermB[p] + gB_);
        }

        #pragma unroll
        for (int ks = 0; ks < 4; ks++) {             // 4 x k16 chunks per BK=64
            const int cur = ks & 1, nxt = cur ^ 1;
            if (ks < 3) {                            // fetch ks+1 before ks's MMAs
                uint32_t gA_ = (uint32_t)(((2 * (ks + 1) + kgA) ^ r8) * 16);
                uint32_t gB_ = (uint32_t)(((2 * (ks + 1) + kgB) ^ r8) * 16);
                #pragma unroll
                for (int mt = 0; mt < 4; mt++) ldsm4(aF[nxt][mt], st + rowTermA[mt] + gA_);
                #pragma unroll
                for (int p = 0; p < 2; p++)    ldsm4(bF[nxt][p],  st + rowTermB[p] + gB_);
            }
            #pragma unroll
            for (int mt = 0; mt < 4; mt++)
                #pragma unroll
                for (int nt = 0; nt < 4; nt++)
                    mma16(acc[mt][nt], aF[cur][mt], &bF[cur][nt >> 1][(nt & 1) * 2]);
        }
    }

    // epilogue: regs -> gmem with bias, float2 stores
    float2 bb[4];
    #pragma unroll
    for (int nt = 0; nt < 4; nt++)
        bb[nt] = *(const float2*)(bias + n0 + nw + nt * 8 + lc * 2);

    #pragma unroll
    for (int mt = 0; mt < 4; mt++) {
        #pragma unroll
        for (int nt = 0; nt < 4; nt++) {
            int m = m0 + mw + mt * 16 + lr;
            int n = n0 + nw + nt * 8 + lc * 2;
            float2 v0 = make_float2(acc[mt][nt][0] + bb[nt].x, acc[mt][nt][1] + bb[nt].y);
            float2 v1 = make_float2(acc[mt][nt][2] + bb[nt].x, acc[mt][nt][3] + bb[nt].y);
            *(float2*)(out + (size_t)m * NDIM + n)       = v0;
            *(float2*)(out + (size_t)(m + 8) * NDIM + n) = v1;
        }
    }
}

// ---------------- launch ------------------------------------------------------
extern "C" void kernel_launch(void* const* d_in, const int* in_sizes, int n_in,
                              void* d_out, int out_size) {
    const float* x  = (const float*)d_in[0];
    const float* W  = (const float*)d_in[1];
    const float* b  = (const float*)d_in[2];
    const float* Aq = (const float*)d_in[3];
    const float* Bq = (const float*)d_in[4];
    const float* Av = (const float*)d_in[5];
    const float* Bv = (const float*)d_in[6];
    const float* lq = (const float*)d_in[7];
    const float* lv = (const float*)d_in[8];
    float* out = (float*)d_out;

    norms_kernel<<<40, 256>>>(Aq, Bq, Av, Bv);
    scales_kernel<<<1, 32>>>(lq, lv);
    build_wc_kernel<<<dim3(12, 36), 256>>>(W, Aq, Bq, Av, Bv);
    cvt_x_kernel<<<4704, 256>>>(x);

    cudaFuncSetAttribute(gemm_kernel, cudaFuncAttributeMaxDynamicSharedMemorySize, SMEM_DYN);
    gemm_kernel<<<dim3(NDIM / 128, MROWS / 128), 256, SMEM_DYN>>>(b, out);
}

// round 16
// speedup vs baseline: 1.7168x; 1.0679x over previous
#include <cuda_runtime.h>
#include <cuda_fp16.h>
#include <cstdint>

#define TAU_F 0.5f

static const int MROWS = 6272;     // 32 * 196
static const int CDIM  = 768;
static const int NDIM  = 2304;     // 3 * 768
static const int TT    = 10;
static const int RRK   = 16;
static const int WC_K  = 192;      // 160 real k + 32 zero pad

// ---------------- device scratch (static allocation is allowed) --------------
__device__ float  g_sumsq[40];                   // [Aq(10) Bq(10) Av(10) Bv(10)]
__device__ __half g_Acat[2 * 768 * WC_K];        // [band][i][k]  k=(t,r), f16
__device__ __half g_Bcat[2 * 768 * WC_K];        // [band][o][k]  scale folded
__device__ __half g_Wch[2304u * 768u];           // W_qkv + LoRA deltas, f16-rn
__device__ __half g_xh [6272u * 768u];           // x, f16-rn

// ---------------- helpers ----------------------------------------------------
__device__ __forceinline__ uint32_t smem_to_u32(const void* smem_ptr) {
    uint32_t addr;
    asm("{ .reg .u64 tmp; cvta.to.shared.u64 tmp, %1; cvt.u32.u64 %0, tmp; }"
        : "=r"(addr) : "l"(smem_ptr));
    return addr;
}

#define CP_ASYNC16(dst, src) \
    asm volatile("cp.async.cg.shared.global [%0], [%1], 16;" :: "r"((uint32_t)(dst)), "l"(src) : "memory")

#define CP_COMMIT() asm volatile("cp.async.commit_group;" ::: "memory")
#define CP_WAIT(n)  asm volatile("cp.async.wait_group %0;" :: "n"(n) : "memory")

// ldmatrix x4 (baseline PTX sm_75+)
__device__ __forceinline__ void ldsm4(uint32_t* r, uint32_t addr) {
    asm volatile("ldmatrix.sync.aligned.m8n8.x4.shared.b16 {%0,%1,%2,%3}, [%4];"
        : "=r"(r[0]), "=r"(r[1]), "=r"(r[2]), "=r"(r[3]) : "r"(addr));
}

// m16n8k16 f16 mma, f32 accumulate (baseline PTX sm_80+): 4096 FLOP/instr
__device__ __forceinline__ void mma16(float* c, const uint32_t* A, const uint32_t* B) {
    asm volatile(
        "mma.sync.aligned.m16n8k16.row.col.f32.f16.f16.f32 "
        "{%0,%1,%2,%3}, {%4,%5,%6,%7}, {%8,%9}, {%0,%1,%2,%3};"
        : "+f"(c[0]), "+f"(c[1]), "+f"(c[2]), "+f"(c[3])
        : "r"(A[0]), "r"(A[1]), "r"(A[2]), "r"(A[3]), "r"(B[0]), "r"(B[1]));
}

// ---------------- prologue kernels -------------------------------------------

// grid 40 x 256: squared Frobenius norms of each [16,768] / [768,16] matrix
__global__ void norms_kernel(const float* __restrict__ Aq, const float* __restrict__ Bq,
                             const float* __restrict__ Av, const float* __restrict__ Bv) {
    const float* mats[4] = {Aq, Bq, Av, Bv};
    int mi = blockIdx.x / 10;
    int t  = blockIdx.x % 10;
    const float* p = mats[mi] + (size_t)t * (RRK * CDIM);
    float s = 0.f;
    for (int i = threadIdx.x; i < RRK * CDIM; i += 256) {
        float v = p[i];
        s += v * v;
    }
    __shared__ float red[256];
    red[threadIdx.x] = s;
    __syncthreads();
    for (int st = 128; st > 0; st >>= 1) {
        if (threadIdx.x < st) red[threadIdx.x] += red[threadIdx.x + st];
        __syncthreads();
    }
    if (threadIdx.x == 0) g_sumsq[blockIdx.x] = red[0];
}

// grid 24 x 256: build f16 concatenated LoRA operands (scales inline).
// bid 0..19: (band, t) fill.  bid 20..23: zero the k-pad [160,192).
__global__ void prep_ab_kernel(const float* __restrict__ Aq, const float* __restrict__ Bq,
                               const float* __restrict__ Av, const float* __restrict__ Bv,
                               const float* __restrict__ lq, const float* __restrict__ lv) {
    const int bid = blockIdx.x, tid = threadIdx.x;

    if (bid >= 20) {                  // zero pads
        int which = bid - 20;         // 0..3
        __half* buf = (which & 1) ? g_Bcat : g_Acat;
        int band = which >> 1;
        for (int idx = tid; idx < 768 * 32; idx += 256) {
            int row = idx >> 5, k = 160 + (idx & 31);
            buf[band * 768 * WC_K + row * WC_K + k] = __ushort_as_half(0);
        }
        return;
    }

    const int band = bid / 10, t = bid % 10;
    const float* A = band ? Av : Aq;
    const float* B = band ? Bv : Bq;

    __shared__ float s_sh;
    if (tid == 0) {                   // fused scale for this task
        const float* l  = band ? lv : lq;
        const float* ss = g_sumsq + band * 20;
        float mx = -1e30f;
        for (int u = 0; u < TT; u++) mx = fmaxf(mx, l[u] / TAU_F);
        float sum = 0.f, et = 0.f;
        for (int u = 0; u < TT; u++) {
            float e = expf(l[u] / TAU_F - mx);
            sum += e;
            if (u == t) et = e;
        }
        s_sh = (et / sum) * rsqrtf(ss[t] * ss[10 + t]);
    }

    // Acat: transpose A[t] (16x768) via smem, write 32B rows per i
    __shared__ __half sA[16 * 768];   // 24KB
    const float* At = A + (size_t)t * 12288;
    for (int idx = tid; idx < 12288; idx += 256)
        sA[idx] = __float2half_rn(At[idx]);           // [r][c]
    __syncthreads();
    float s = s_sh;
    for (int c = tid; c < 768; c += 256) {
        __align__(16) __half tmp[16];
        #pragma unroll
        for (int r = 0; r < 16; r++) tmp[r] = sA[r * 768 + c];
        __half* dst = g_Acat + band * 768 * WC_K + c * WC_K + t * 16;
        *(uint4*)(dst)     = *(uint4*)(tmp);
        *(uint4*)(dst + 8) = *(uint4*)(tmp + 8);
    }
    // Bcat: B[t][o][r] contiguous reads, 32B-chunk writes, scale folded
    const float* Bt = B + (size_t)t * 12288;
    for (int idx = tid; idx < 12288; idx += 256) {
        int o = idx >> 4, r = idx & 15;
        g_Bcat[band * 768 * WC_K + o * WC_K + t * 16 + r] = __float2half_rn(Bt[idx] * s);
    }
}

// grid (6, 12) x 256: Wc[band rows] = f16(W + Bcat·Acat^T), K=192 f16 mma GEMM.
// Same 128x128 / 8-warp / ldmatrix structure as the main GEMM.
static const int STAGE_BYTES = 32768;     // A 16KB + B 16KB
static const int SMEM_DYN = 3 * STAGE_BYTES;

__global__ void __launch_bounds__(256, 2)
wc_mma_kernel(const float* __restrict__ W) {
    extern __shared__ char smem[];
    const uint32_t sbase = smem_to_u32(smem);

    const int tid = threadIdx.x;
    const int wid = tid >> 5, lid = tid & 31;
    const int lr  = lid >> 2, lc = lid & 3;
    const int sub = lid >> 3, r8 = lid & 7;
    const int n0  = blockIdx.x * 128;                // i dim (0..767)
    const int band = (blockIdx.y >= 6);              // 0=q rows, 1=v rows
    const int m0  = (blockIdx.y % 6) * 128;          // o within band

    const __half* gA = g_Bcat + band * 768 * WC_K + (size_t)m0 * WC_K;
    const __half* gB = g_Acat + band * 768 * WC_K + (size_t)n0 * WC_K;

    const int lrow = tid >> 3;
    const int lc8  = tid & 7;

    auto load_stage = [&](int s) {
        uint32_t st = sbase + (uint32_t)(s % 3) * STAGE_BYTES;
        int k0 = s * 64;
        #pragma unroll
        for (int q = 0; q < 4; q++) {
            int row = lrow + q * 32;
            uint32_t off = (uint32_t)row * 128 + (uint32_t)(lc8 ^ (row & 7)) * 16;
            CP_ASYNC16(st + off,         gA + (size_t)row * WC_K + k0 + lc8 * 8);
            CP_ASYNC16(st + 16384 + off, gB + (size_t)row * WC_K + k0 + lc8 * 8);
        }
    };

    const int kgA = sub >> 1;
    uint32_t rowTermA[4];
    #pragma unroll
    for (int mt = 0; mt < 4; mt++)
        rowTermA[mt] = (uint32_t)((wid & 1) * 64 + mt * 16 + (sub & 1) * 8 + r8) * 128;
    const int kgB = sub & 1;
    uint32_t rowTermB[2];
    #pragma unroll
    for (int p = 0; p < 2; p++)
        rowTermB[p] = 16384u + (uint32_t)((wid >> 1) * 32 + p * 16 + (sub >> 1) * 8 + r8) * 128;

    float acc[4][4][4] = {};

    load_stage(0); CP_COMMIT();
    load_stage(1); CP_COMMIT();

    for (int i = 0; i < 3; ++i) {                    // KT = 3
        CP_WAIT(1);
        __syncthreads();
        if (i + 2 < 3) load_stage(i + 2);
        CP_COMMIT();

        uint32_t st = sbase + (uint32_t)(i % 3) * STAGE_BYTES;
        #pragma unroll
        for (int ks = 0; ks < 4; ks++) {
            uint32_t gA_ = (uint32_t)(((2 * ks + kgA) ^ r8) * 16);
            uint32_t gB_ = (uint32_t)(((2 * ks + kgB) ^ r8) * 16);
            uint32_t a[4][4];
            #pragma unroll
            for (int mt = 0; mt < 4; mt++) ldsm4(a[mt], st + rowTermA[mt] + gA_);
            uint32_t b[2][4];
            #pragma unroll
            for (int p = 0; p < 2; p++)    ldsm4(b[p],  st + rowTermB[p] + gB_);
            #pragma unroll
            for (int mt = 0; mt < 4; mt++)
                #pragma unroll
                for (int nt = 0; nt < 4; nt++)
                    mma16(acc[mt][nt], a[mt], &b[nt >> 1][(nt & 1) * 2]);
        }
    }

    // epilogue: Wc = f16(W + acc)
    const int mw = (wid & 1) * 64, nw = (wid >> 1) * 32;
    const int row_base = band ? 1536 : 0;
    #pragma unroll
    for (int mt = 0; mt < 4; mt++) {
        #pragma unroll
        for (int nt = 0; nt < 4; nt++) {
            int mg = row_base + m0 + mw + mt * 16 + lr;
            int n  = n0 + nw + nt * 8 + lc * 2;
            float2 w0 = *(const float2*)(W + (size_t)mg * CDIM + n);
            float2 w1 = *(const float2*)(W + (size_t)(mg + 8) * CDIM + n);
            __half2 h0 = __floats2half2_rn(acc[mt][nt][0] + w0.x, acc[mt][nt][1] + w0.y);
            __half2 h1 = __floats2half2_rn(acc[mt][nt][2] + w1.x, acc[mt][nt][3] + w1.y);
            *(__half2*)(g_Wch + (size_t)mg * CDIM + n)       = h0;
            *(__half2*)(g_Wch + (size_t)(mg + 8) * CDIM + n) = h1;
        }
    }
}

// grid 4992 x 256: blocks [0,4704) x->f16; blocks [4704,4992) copy W k-band
__global__ void cvtx_copy_kernel(const float* __restrict__ x, const float* __restrict__ W) {
    const int b = blockIdx.x, tid = threadIdx.x;
    if (b < 4704) {
        int i = b * 256 + tid;                        // exactly MROWS*CDIM/4
        float4 v = ((const float4*)x)[i];
        __half2 h0 = __floats2half2_rn(v.x, v.y);
        __half2 h1 = __floats2half2_rn(v.z, v.w);
        uint2 pk;
        pk.x = *reinterpret_cast<uint32_t*>(&h0);
        pk.y = *reinterpret_cast<uint32_t*>(&h1);
        ((uint2*)g_xh)[i] = pk;
        return;
    }
    // W rows 768..1535 (k band): 768*768 f32 = 147456 float4, 2 per thread
    const int base = 147456;                          // float4 offset of band 1
    #pragma unroll
    for (int u = 0; u < 2; u++) {
        int j = (b - 4704) * 512 + u * 256 + tid;     // 0..147455
        float4 v = ((const float4*)W)[base + j];
        __half2 h0 = __floats2half2_rn(v.x, v.y);
        __half2 h1 = __floats2half2_rn(v.z, v.w);
        uint2 pk;
        pk.x = *reinterpret_cast<uint32_t*>(&h0);
        pk.y = *reinterpret_cast<uint32_t*>(&h1);
        ((uint2*)g_Wch)[base + j] = pk;
    }
}

// ---------------- main GEMM (R14 best: 128x128, BK=64, frag double-buffer) ---
static const int KT = CDIM / 64;          // 12 k-tiles

__global__ void __launch_bounds__(256, 2)
gemm_kernel(const float* __restrict__ bias, float* __restrict__ out) {
    extern __shared__ char smem[];
    const uint32_t sbase = smem_to_u32(smem);

    const int tid = threadIdx.x;
    const int wid = tid >> 5, lid = tid & 31;
    const int lr  = lid >> 2, lc = lid & 3;
    const int sub = lid >> 3, r8 = lid & 7;
    const int n0  = blockIdx.x * 128;
    const int m0  = blockIdx.y * 128;
    const int mw  = (wid & 1) * 64;
    const int nw  = (wid >> 1) * 32;

    const __half* gA = g_xh  + (size_t)m0 * CDIM;
    const __half* gB = g_Wch + (size_t)n0 * CDIM;

    const int lrow = tid >> 3;
    const int lc8  = tid & 7;

    auto load_stage = [&](int s) {
        uint32_t st = sbase + (uint32_t)(s % 3) * STAGE_BYTES;
        int k0 = s * 64;
        #pragma unroll
        for (int q = 0; q < 4; q++) {
            int row = lrow + q * 32;
            uint32_t off = (uint32_t)row * 128 + (uint32_t)(lc8 ^ (row & 7)) * 16;
            CP_ASYNC16(st + off, gA + (size_t)row * CDIM + k0 + lc8 * 8);
        }
        #pragma unroll
        for (int q = 0; q < 4; q++) {
            int row = lrow + q * 32;
            uint32_t off = (uint32_t)row * 128 + (uint32_t)(lc8 ^ (row & 7)) * 16;
            CP_ASYNC16(st + 16384 + off, gB + (size_t)row * CDIM + k0 + lc8 * 8);
        }
    };

    const int kgA = sub >> 1;
    uint32_t rowTermA[4];
    #pragma unroll
    for (int mt = 0; mt < 4; mt++)
        rowTermA[mt] = (uint32_t)(mw + mt * 16 + (sub & 1) * 8 + r8) * 128;
    const int kgB = sub & 1;
    uint32_t rowTermB[2];
    #pragma unroll
    for (int p = 0; p < 2; p++)
        rowTermB[p] = 16384u + (uint32_t)(nw + p * 16 + (sub >> 1) * 8 + r8) * 128;

    float acc[4][4][4] = {};
    uint32_t aF[2][4][4];
    uint32_t bF[2][2][4];

    load_stage(0); CP_COMMIT();
    load_stage(1); CP_COMMIT();

    for (int i = 0; i < KT; ++i) {
        CP_WAIT(1);
        __syncthreads();
        if (i + 2 < KT) load_stage(i + 2);
        CP_COMMIT();

        uint32_t st = sbase + (uint32_t)(i % 3) * STAGE_BYTES;

        {
            uint32_t gA_ = (uint32_t)((kgA ^ r8) * 16);
            uint32_t gB_ = (uint32_t)((kgB ^ r8) * 16);
            #pragma unroll
            for (int mt = 0; mt < 4; mt++) ldsm4(aF[0][mt], st + rowTermA[mt] + gA_);
            #pragma unroll
            for (int p = 0; p < 2; p++)    ldsm4(bF[0][p],  st + rowTermB[p] + gB_);
        }

        #pragma unroll
        for (int ks = 0; ks < 4; ks++) {
            const int cur = ks & 1, nxt = cur ^ 1;
            if (ks < 3) {
                uint32_t gA_ = (uint32_t)(((2 * (ks + 1) + kgA) ^ r8) * 16);
                uint32_t gB_ = (uint32_t)(((2 * (ks + 1) + kgB) ^ r8) * 16);
                #pragma unroll
                for (int mt = 0; mt < 4; mt++) ldsm4(aF[nxt][mt], st + rowTermA[mt] + gA_);
                #pragma unroll
                for (int p = 0; p < 2; p++)    ldsm4(bF[nxt][p],  st + rowTermB[p] + gB_);
            }
            #pragma unroll
            for (int mt = 0; mt < 4; mt++)
                #pragma unroll
                for (int nt = 0; nt < 4; nt++)
                    mma16(acc[mt][nt], aF[cur][mt], &bF[cur][nt >> 1][(nt & 1) * 2]);
        }
    }

    float2 bb[4];
    #pragma unroll
    for (int nt = 0; nt < 4; nt++)
        bb[nt] = *(const float2*)(bias + n0 + nw + nt * 8 + lc * 2);

    #pragma unroll
    for (int mt = 0; mt < 4; mt++) {
        #pragma unroll
        for (int nt = 0; nt < 4; nt++) {
            int m = m0 + mw + mt * 16 + lr;
            int n = n0 + nw + nt * 8 + lc * 2;
            float2 v0 = make_float2(acc[mt][nt][0] + bb[nt].x, acc[mt][nt][1] + bb[nt].y);
            float2 v1 = make_float2(acc[mt][nt][2] + bb[nt].x, acc[mt][nt][3] + bb[nt].y);
            *(float2*)(out + (size_t)m * NDIM + n)       = v0;
            *(float2*)(out + (size_t)(m + 8) * NDIM + n) = v1;
        }
    }
}

// ---------------- launch ------------------------------------------------------
extern "C" void kernel_launch(void* const* d_in, const int* in_sizes, int n_in,
                              void* d_out, int out_size) {
    const float* x  = (const float*)d_in[0];
    const float* W  = (const float*)d_in[1];
    const float* b  = (const float*)d_in[2];
    const float* Aq = (const float*)d_in[3];
    const float* Bq = (const float*)d_in[4];
    const float* Av = (const float*)d_in[5];
    const float* Bv = (const float*)d_in[6];
    const float* lq = (const float*)d_in[7];
    const float* lv = (const float*)d_in[8];
    float* out = (float*)d_out;

    norms_kernel<<<40, 256>>>(Aq, Bq, Av, Bv);
    prep_ab_kernel<<<24, 256>>>(Aq, Bq, Av, Bv, lq, lv);

    cudaFuncSetAttribute(wc_mma_kernel, cudaFuncAttributeMaxDynamicSharedMemorySize, SMEM_DYN);
    wc_mma_kernel<<<dim3(6, 12), 256, SMEM_DYN>>>(W);

    cvtx_copy_kernel<<<4992, 256>>>(x, W);

    cudaFuncSetAttribute(gemm_kernel, cudaFuncAttributeMaxDynamicSharedMemorySize, SMEM_DYN);
    gemm_kernel<<<dim3(NDIM / 128, MROWS / 128), 256, SMEM_DYN>>>(b, out);
}

// round 17
// speedup vs baseline: 1.8353x; 1.0690x over previous
#include <cuda_runtime.h>
#include <cuda_fp16.h>
#include <cstdint>

#define TAU_F 0.5f

static const int MROWS = 6272;     // 32 * 196
static const int CDIM  = 768;
static const int NDIM  = 2304;     // 3 * 768
static const int TT    = 10;
static const int RRK   = 16;
static const int WC_K  = 192;      // 160 real k + 32 zero pad

// ---------------- device scratch (static allocation is allowed) --------------
__device__ __half g_Acat[2 * 768 * WC_K];        // [band][i][k]  k=(t,r), f16
__device__ __half g_Bcat[2 * 768 * WC_K];        // [band][o][k]  scale folded
__device__ __half g_Wch[2304u * 768u];           // W_qkv + LoRA deltas, f16-rn
__device__ __half g_xh [6272u * 768u];           // x, f16-rn

// ---------------- helpers ----------------------------------------------------
__device__ __forceinline__ uint32_t smem_to_u32(const void* smem_ptr) {
    uint32_t addr;
    asm("{ .reg .u64 tmp; cvta.to.shared.u64 tmp, %1; cvt.u32.u64 %0, tmp; }"
        : "=r"(addr) : "l"(smem_ptr));
    return addr;
}

#define CP_ASYNC16(dst, src) \
    asm volatile("cp.async.cg.shared.global [%0], [%1], 16;" :: "r"((uint32_t)(dst)), "l"(src) : "memory")

#define CP_COMMIT() asm volatile("cp.async.commit_group;" ::: "memory")
#define CP_WAIT(n)  asm volatile("cp.async.wait_group %0;" :: "n"(n) : "memory")

// ldmatrix x4 (baseline PTX sm_75+)
__device__ __forceinline__ void ldsm4(uint32_t* r, uint32_t addr) {
    asm volatile("ldmatrix.sync.aligned.m8n8.x4.shared.b16 {%0,%1,%2,%3}, [%4];"
        : "=r"(r[0]), "=r"(r[1]), "=r"(r[2]), "=r"(r[3]) : "r"(addr));
}

// m16n8k16 f16 mma, f32 accumulate (baseline PTX sm_80+): 4096 FLOP/instr
__device__ __forceinline__ void mma16(float* c, const uint32_t* A, const uint32_t* B) {
    asm volatile(
        "mma.sync.aligned.m16n8k16.row.col.f32.f16.f16.f32 "
        "{%0,%1,%2,%3}, {%4,%5,%6,%7}, {%8,%9}, {%0,%1,%2,%3};"
        : "+f"(c[0]), "+f"(c[1]), "+f"(c[2]), "+f"(c[3])
        : "r"(A[0]), "r"(A[1]), "r"(A[2]), "r"(A[3]), "r"(B[0]), "r"(B[1]));
}

// ---------------- prologue kernels -------------------------------------------

// grid 24 x 256: build f16 concatenated LoRA operands; Frobenius norms and
// softmax scales computed inline (each (band,t) block needs only its OWN norms
// plus the 10 logits, and it already reads A[t], B[t] in full).
// bid 0..19: (band, t) fill.  bid 20..23: zero the k-pad [160,192).
static const int PREP_SMEM = 16 * 768 * 2 + 768 * 16 * 4;   // sA f16 + sBf f32 = 73728

__global__ void __launch_bounds__(256)
prep_ab_kernel(const float* __restrict__ Aq, const float* __restrict__ Bq,
               const float* __restrict__ Av, const float* __restrict__ Bv,
               const float* __restrict__ lq, const float* __restrict__ lv) {
    const int bid = blockIdx.x, tid = threadIdx.x;

    if (bid >= 20) {                  // zero pads
        int which = bid - 20;         // 0..3
        __half* buf = (which & 1) ? g_Bcat : g_Acat;
        int band = which >> 1;
        for (int idx = tid; idx < 768 * 32; idx += 256) {
            int row = idx >> 5, k = 160 + (idx & 31);
            buf[band * 768 * WC_K + row * WC_K + k] = __ushort_as_half(0);
        }
        return;
    }

    extern __shared__ char psm[];
    __half* sA  = (__half*)psm;                       // [16][768] f16  (24KB)
    float*  sBf = (float*)(psm + 24576);              // [768][16] f32  (48KB)
    __shared__ float redA[256], redB[256];
    __shared__ float s_sh;

    const int band = bid / 10, t = bid % 10;
    const float* At = (band ? Av : Aq) + (size_t)t * 12288;
    const float* Bt = (band ? Bv : Bq) + (size_t)t * 12288;

    // single pass: stage + accumulate squared norms (same summation order as
    // the old norms_kernel -> numerically identical scales)
    float ssA = 0.f, ssB = 0.f;
    for (int idx = tid; idx < 12288; idx += 256) {
        float va = At[idx];
        ssA += va * va;
        sA[idx] = __float2half_rn(va);
        float vb = Bt[idx];
        ssB += vb * vb;
        sBf[idx] = vb;
    }
    redA[tid] = ssA;
    redB[tid] = ssB;
    __syncthreads();
    for (int st = 128; st > 0; st >>= 1) {
        if (tid < st) { redA[tid] += redA[tid + st]; redB[tid] += redB[tid + st]; }
        __syncthreads();
    }
    if (tid == 0) {                   // fused scale for this task
        const float* l = band ? lv : lq;
        float mx = -1e30f;
        for (int u = 0; u < TT; u++) mx = fmaxf(mx, l[u] / TAU_F);
        float sum = 0.f, et = 0.f;
        for (int u = 0; u < TT; u++) {
            float e = expf(l[u] / TAU_F - mx);
            sum += e;
            if (u == t) et = e;
        }
        s_sh = (et / sum) * rsqrtf(redA[0] * redB[0]);
    }
    __syncthreads();
    float s = s_sh;

    // Acat: transpose A[t] via smem, 32B per i (scale NOT folded here)
    for (int c = tid; c < 768; c += 256) {
        __align__(16) __half tmp[16];
        #pragma unroll
        for (int r = 0; r < 16; r++) tmp[r] = sA[r * 768 + c];
        __half* dst = g_Acat + band * 768 * WC_K + c * WC_K + t * 16;
        *(uint4*)(dst)     = *(uint4*)(tmp);
        *(uint4*)(dst + 8) = *(uint4*)(tmp + 8);
    }
    // Bcat: scale folded, single f32->f16 rounding
    for (int idx = tid; idx < 12288; idx += 256) {
        int o = idx >> 4, r = idx & 15;
        g_Bcat[band * 768 * WC_K + o * WC_K + t * 16 + r] = __float2half_rn(sBf[idx] * s);
    }
}

// grid (6, 12) x 256: Wc[band rows] = f16(W + Bcat·Acat^T), K=192 f16 mma GEMM.
static const int STAGE_BYTES = 32768;     // A 16KB + B 16KB
static const int SMEM_DYN = 3 * STAGE_BYTES;

__global__ void __launch_bounds__(256, 2)
wc_mma_kernel(const float* __restrict__ W) {
    extern __shared__ char smem[];
    const uint32_t sbase = smem_to_u32(smem);

    const int tid = threadIdx.x;
    const int wid = tid >> 5, lid = tid & 31;
    const int lr  = lid >> 2, lc = lid & 3;
    const int sub = lid >> 3, r8 = lid & 7;
    const int n0  = blockIdx.x * 128;                // i dim (0..767)
    const int band = (blockIdx.y >= 6);              // 0=q rows, 1=v rows
    const int m0  = (blockIdx.y % 6) * 128;          // o within band

    const __half* gA = g_Bcat + band * 768 * WC_K + (size_t)m0 * WC_K;
    const __half* gB = g_Acat + band * 768 * WC_K + (size_t)n0 * WC_K;

    const int lrow = tid >> 3;
    const int lc8  = tid & 7;

    auto load_stage = [&](int s) {
        uint32_t st = sbase + (uint32_t)(s % 3) * STAGE_BYTES;
        int k0 = s * 64;
        #pragma unroll
        for (int q = 0; q < 4; q++) {
            int row = lrow + q * 32;
            uint32_t off = (uint32_t)row * 128 + (uint32_t)(lc8 ^ (row & 7)) * 16;
            CP_ASYNC16(st + off,         gA + (size_t)row * WC_K + k0 + lc8 * 8);
            CP_ASYNC16(st + 16384 + off, gB + (size_t)row * WC_K + k0 + lc8 * 8);
        }
    };

    const int kgA = sub >> 1;
    uint32_t rowTermA[4];
    #pragma unroll
    for (int mt = 0; mt < 4; mt++)
        rowTermA[mt] = (uint32_t)((wid & 1) * 64 + mt * 16 + (sub & 1) * 8 + r8) * 128;
    const int kgB = sub & 1;
    uint32_t rowTermB[2];
    #pragma unroll
    for (int p = 0; p < 2; p++)
        rowTermB[p] = 16384u + (uint32_t)((wid >> 1) * 32 + p * 16 + (sub >> 1) * 8 + r8) * 128;

    float acc[4][4][4] = {};

    load_stage(0); CP_COMMIT();
    load_stage(1); CP_COMMIT();

    for (int i = 0; i < 3; ++i) {                    // KT = 3
        CP_WAIT(1);
        __syncthreads();
        if (i + 2 < 3) load_stage(i + 2);
        CP_COMMIT();

        uint32_t st = sbase + (uint32_t)(i % 3) * STAGE_BYTES;
        #pragma unroll
        for (int ks = 0; ks < 4; ks++) {
            uint32_t gA_ = (uint32_t)(((2 * ks + kgA) ^ r8) * 16);
            uint32_t gB_ = (uint32_t)(((2 * ks + kgB) ^ r8) * 16);
            uint32_t a[4][4];
            #pragma unroll
            for (int mt = 0; mt < 4; mt++) ldsm4(a[mt], st + rowTermA[mt] + gA_);
            uint32_t b[2][4];
            #pragma unroll
            for (int p = 0; p < 2; p++)    ldsm4(b[p],  st + rowTermB[p] + gB_);
            #pragma unroll
            for (int mt = 0; mt < 4; mt++)
                #pragma unroll
                for (int nt = 0; nt < 4; nt++)
                    mma16(acc[mt][nt], a[mt], &b[nt >> 1][(nt & 1) * 2]);
        }
    }

    // epilogue: Wc = f16(W + acc)
    const int mw = (wid & 1) * 64, nw = (wid >> 1) * 32;
    const int row_base = band ? 1536 : 0;
    #pragma unroll
    for (int mt = 0; mt < 4; mt++) {
        #pragma unroll
        for (int nt = 0; nt < 4; nt++) {
            int mg = row_base + m0 + mw + mt * 16 + lr;
            int n  = n0 + nw + nt * 8 + lc * 2;
            float2 w0 = *(const float2*)(W + (size_t)mg * CDIM + n);
            float2 w1 = *(const float2*)(W + (size_t)(mg + 8) * CDIM + n);
            __half2 h0 = __floats2half2_rn(acc[mt][nt][0] + w0.x, acc[mt][nt][1] + w0.y);
            __half2 h1 = __floats2half2_rn(acc[mt][nt][2] + w1.x, acc[mt][nt][3] + w1.y);
            *(__half2*)(g_Wch + (size_t)mg * CDIM + n)       = h0;
            *(__half2*)(g_Wch + (size_t)(mg + 8) * CDIM + n) = h1;
        }
    }
}

// grid 1320 x 256, 4 independent float4 per thread (MLP=4, exact cover):
// items [0, 1204224): x -> f16;  items [1204224, 1351680): W k-band copy
static const int CVT_XN    = MROWS * CDIM / 4;      // 1204224
static const int CVT_WBASE = 147456;                // float4 offset of W band 1
static const int CVT_TOT   = CVT_XN + 147456;       // 1351680
static const int CVT_BLK   = 1320;                  // 1320*256*4 == CVT_TOT

__global__ void __launch_bounds__(256)
cvtx_copy_kernel(const float* __restrict__ x, const float* __restrict__ W) {
    const int gtid = blockIdx.x * 256 + threadIdx.x;
    const int stride = CVT_BLK * 256;                // 337920
    #pragma unroll
    for (int u = 0; u < 4; u++) {
        int i = gtid + u * stride;
        bool isx = (i < CVT_XN);
        const float4* src = isx ? ((const float4*)x) + i
                                : ((const float4*)W) + (CVT_WBASE + (i - CVT_XN));
        float4 v = *src;
        __half2 h0 = __floats2half2_rn(v.x, v.y);
        __half2 h1 = __floats2half2_rn(v.z, v.w);
        uint2 pk;
        pk.x = *reinterpret_cast<uint32_t*>(&h0);
        pk.y = *reinterpret_cast<uint32_t*>(&h1);
        uint2* dst = isx ? ((uint2*)g_xh) + i
                         : ((uint2*)g_Wch) + (CVT_WBASE + (i - CVT_XN));
        *dst = pk;
    }
}

// ---------------- main GEMM (R14/R16 best: 128x128, BK=64, frag dbuf) --------
static const int KT = CDIM / 64;          // 12 k-tiles

__global__ void __launch_bounds__(256, 2)
gemm_kernel(const float* __restrict__ bias, float* __restrict__ out) {
    extern __shared__ char smem[];
    const uint32_t sbase = smem_to_u32(smem);

    const int tid = threadIdx.x;
    const int wid = tid >> 5, lid = tid & 31;
    const int lr  = lid >> 2, lc = lid & 3;
    const int sub = lid >> 3, r8 = lid & 7;
    const int n0  = blockIdx.x * 128;
    const int m0  = blockIdx.y * 128;
    const int mw  = (wid & 1) * 64;
    const int nw  = (wid >> 1) * 32;

    const __half* gA = g_xh  + (size_t)m0 * CDIM;
    const __half* gB = g_Wch + (size_t)n0 * CDIM;

    const int lrow = tid >> 3;
    const int lc8  = tid & 7;

    auto load_stage = [&](int s) {
        uint32_t st = sbase + (uint32_t)(s % 3) * STAGE_BYTES;
        int k0 = s * 64;
        #pragma unroll
        for (int q = 0; q < 4; q++) {
            int row = lrow + q * 32;
            uint32_t off = (uint32_t)row * 128 + (uint32_t)(lc8 ^ (row & 7)) * 16;
            CP_ASYNC16(st + off, gA + (size_t)row * CDIM + k0 + lc8 * 8);
        }
        #pragma unroll
        for (int q = 0; q < 4; q++) {
            int row = lrow + q * 32;
            uint32_t off = (uint32_t)row * 128 + (uint32_t)(lc8 ^ (row & 7)) * 16;
            CP_ASYNC16(st + 16384 + off, gB + (size_t)row * CDIM + k0 + lc8 * 8);
        }
    };

    const int kgA = sub >> 1;
    uint32_t rowTermA[4];
    #pragma unroll
    for (int mt = 0; mt < 4; mt++)
        rowTermA[mt] = (uint32_t)(mw + mt * 16 + (sub & 1) * 8 + r8) * 128;
    const int kgB = sub & 1;
    uint32_t rowTermB[2];
    #pragma unroll
    for (int p = 0; p < 2; p++)
        rowTermB[p] = 16384u + (uint32_t)(nw + p * 16 + (sub >> 1) * 8 + r8) * 128;

    float acc[4][4][4] = {};
    uint32_t aF[2][4][4];
    uint32_t bF[2][2][4];

    load_stage(0); CP_COMMIT();
    load_stage(1); CP_COMMIT();

    for (int i = 0; i < KT; ++i) {
        CP_WAIT(1);
        __syncthreads();
        if (i + 2 < KT) load_stage(i + 2);
        CP_COMMIT();

        uint32_t st = sbase + (uint32_t)(i % 3) * STAGE_BYTES;

        {
            uint32_t gA_ = (uint32_t)((kgA ^ r8) * 16);
            uint32_t gB_ = (uint32_t)((kgB ^ r8) * 16);
            #pragma unroll
            for (int mt = 0; mt < 4; mt++) ldsm4(aF[0][mt], st + rowTermA[mt] + gA_);
            #pragma unroll
            for (int p = 0; p < 2; p++)    ldsm4(bF[0][p],  st + rowTermB[p] + gB_);
        }

        #pragma unroll
        for (int ks = 0; ks < 4; ks++) {
            const int cur = ks & 1, nxt = cur ^ 1;
            if (ks < 3) {
                uint32_t gA_ = (uint32_t)(((2 * (ks + 1) + kgA) ^ r8) * 16);
                uint32_t gB_ = (uint32_t)(((2 * (ks + 1) + kgB) ^ r8) * 16);
                #pragma unroll
                for (int mt = 0; mt < 4; mt++) ldsm4(aF[nxt][mt], st + rowTermA[mt] + gA_);
                #pragma unroll
                for (int p = 0; p < 2; p++)    ldsm4(bF[nxt][p],  st + rowTermB[p] + gB_);
            }
            #pragma unroll
            for (int mt = 0; mt < 4; mt++)
                #pragma unroll
                for (int nt = 0; nt < 4; nt++)
                    mma16(acc[mt][nt], aF[cur][mt], &bF[cur][nt >> 1][(nt & 1) * 2]);
        }
    }

    float2 bb[4];
    #pragma unroll
    for (int nt = 0; nt < 4; nt++)
        bb[nt] = *(const float2*)(bias + n0 + nw + nt * 8 + lc * 2);

    #pragma unroll
    for (int mt = 0; mt < 4; mt++) {
        #pragma unroll
        for (int nt = 0; nt < 4; nt++) {
            int m = m0 + mw + mt * 16 + lr;
            int n = n0 + nw + nt * 8 + lc * 2;
            float2 v0 = make_float2(acc[mt][nt][0] + bb[nt].x, acc[mt][nt][1] + bb[nt].y);
            float2 v1 = make_float2(acc[mt][nt][2] + bb[nt].x, acc[mt][nt][3] + bb[nt].y);
            *(float2*)(out + (size_t)m * NDIM + n)       = v0;
            *(float2*)(out + (size_t)(m + 8) * NDIM + n) = v1;
        }
    }
}

// ---------------- launch ------------------------------------------------------
extern "C" void kernel_launch(void* const* d_in, const int* in_sizes, int n_in,
                              void* d_out, int out_size) {
    const float* x  = (const float*)d_in[0];
    const float* W  = (const float*)d_in[1];
    const float* b  = (const float*)d_in[2];
    const float* Aq = (const float*)d_in[3];
    const float* Bq = (const float*)d_in[4];
    const float* Av = (const float*)d_in[5];
    const float* Bv = (const float*)d_in[6];
    const float* lq = (const float*)d_in[7];
    const float* lv = (const float*)d_in[8];
    float* out = (float*)d_out;

    cudaFuncSetAttribute(prep_ab_kernel, cudaFuncAttributeMaxDynamicSharedMemorySize, PREP_SMEM);
    prep_ab_kernel<<<24, 256, PREP_SMEM>>>(Aq, Bq, Av, Bv, lq, lv);

    cudaFuncSetAttribute(wc_mma_kernel, cudaFuncAttributeMaxDynamicSharedMemorySize, SMEM_DYN);
    wc_mma_kernel<<<dim3(6, 12), 256, SMEM_DYN>>>(W);

    cvtx_copy_kernel<<<CVT_BLK, 256>>>(x, W);

    cudaFuncSetAttribute(gemm_kernel, cudaFuncAttributeMaxDynamicSharedMemorySize, SMEM_DYN);
    gemm_kernel<<<dim3(NDIM / 128, MROWS / 128), 256, SMEM_DYN>>>(b, out);
}